// round 3
// baseline (speedup 1.0000x reference)
#include <cuda_runtime.h>

// Problem constants: B=4, N=128, M=128, D=256, BD=1024
#define Bsz 4
#define Nn  128
#define Mm  128
#define Dd  256
#define BD  1024

// Scratch: allocation-free per harness rules -> __device__ globals.
__device__ float g_Aw[Dd * Dd];          // 256 KB: Aw[d,e] = sum_k A[d,e,k]*W[k]
__device__ float g_T[Bsz * Nn * Dd];     // 512 KB: T[b,n,e] = sum_d X[b,n,d]*Aw[d,e]

// ---------------------------------------------------------------------------
// Kernel 1 (the 268 MB pass): Aw[de] = dot(A[de, 0:1024], W[0:1024])
// TWO rows per warp -> 16 LDG.128 in flight per warp (double the MLP of R2's
// version, which sat at 81% DRAM with issue=13.8%). __ldcs: A is touch-once.
// ---------------------------------------------------------------------------
__global__ void __launch_bounds__(256) k_reduce_A(const float* __restrict__ A,
                                                  const float* __restrict__ W) {
    __shared__ float4 ws[BD / 4];  // 4 KB staged W
    int tid = threadIdx.x;
    ws[tid] = ((const float4*)W)[tid];
    __syncthreads();

    int warp = tid >> 5;
    int lane = tid & 31;
    long base = (long)blockIdx.x * 16 + warp * 2;      // 2 rows per warp
    const float4* a0 = (const float4*)A + base * (BD / 4);
    const float4* a1 = a0 + (BD / 4);

    float s0 = 0.0f, s1 = 0.0f;
#pragma unroll
    for (int i = 0; i < 8; i++) {
        float4 v0 = __ldcs(&a0[lane + 32 * i]);
        float4 v1 = __ldcs(&a1[lane + 32 * i]);
        float4 wv = ws[lane + 32 * i];
        s0 += v0.x * wv.x + v0.y * wv.y + v0.z * wv.z + v0.w * wv.w;
        s1 += v1.x * wv.x + v1.y * wv.y + v1.z * wv.z + v1.w * wv.w;
    }
#pragma unroll
    for (int o = 16; o; o >>= 1) {
        s0 += __shfl_xor_sync(0xFFFFFFFFu, s0, o);
        s1 += __shfl_xor_sync(0xFFFFFFFFu, s1, o);
    }
    if (lane == 0) {
        g_Aw[base + 0] = s0;
        g_Aw[base + 1] = s1;
    }
    // PDL: let kernel 2's prologue (X staging) overlap our tail wave.
    cudaTriggerProgrammaticLaunchCompletion();
}

// ---------------------------------------------------------------------------
// Kernel 2: T = Xflat[512,256] @ Aw[256,256]
// PDL-structured: stage the full 32x256 X strip BEFORE the grid-dep sync,
// touch g_Aw only after. 32x32 tile, 2x2 micro-tile per thread.
// ---------------------------------------------------------------------------
__global__ void __launch_bounds__(256) k_gemm_XA(const float* __restrict__ X) {
    __shared__ float xs[32][257];   // full K strip of X rows (padded)
    __shared__ float as[32][33];    // Aw tile [k][col]
    int tx = threadIdx.x, ty = threadIdx.y;      // 16x16
    int tid = ty * 16 + tx;
    int row0 = blockIdx.y * 32;                  // b*n flattened (0..511)
    int col0 = blockIdx.x * 32;                  // e (0..255)

    // Stage X strip (independent of upstream kernel) — 32 rows x 64 float4
    for (int i = tid; i < 32 * 64; i += 256) {
        int r = i >> 6, c4 = i & 63;
        float4 v = ((const float4*)(X + (long)(row0 + r) * Dd))[c4];
        xs[r][c4 * 4 + 0] = v.x; xs[r][c4 * 4 + 1] = v.y;
        xs[r][c4 * 4 + 2] = v.z; xs[r][c4 * 4 + 3] = v.w;
    }
    cudaGridDependencySynchronize();   // g_Aw now visible
    __syncthreads();

    float acc00 = 0.f, acc01 = 0.f, acc10 = 0.f, acc11 = 0.f;
    for (int t = 0; t < Dd; t += 32) {
#pragma unroll
        for (int i = 0; i < 2; i++)
#pragma unroll
            for (int j = 0; j < 2; j++)
                as[ty * 2 + i][tx * 2 + j] = g_Aw[(t + ty * 2 + i) * Dd + col0 + tx * 2 + j];
        __syncthreads();
#pragma unroll
        for (int k = 0; k < 32; k++) {
            float x0 = xs[ty * 2 + 0][t + k];
            float x1 = xs[ty * 2 + 1][t + k];
            float a0 = as[k][tx * 2 + 0];
            float a1 = as[k][tx * 2 + 1];
            acc00 += x0 * a0; acc01 += x0 * a1;
            acc10 += x1 * a0; acc11 += x1 * a1;
        }
        __syncthreads();
    }
    g_T[(row0 + ty * 2 + 0) * Dd + col0 + tx * 2 + 0] = acc00;
    g_T[(row0 + ty * 2 + 0) * Dd + col0 + tx * 2 + 1] = acc01;
    g_T[(row0 + ty * 2 + 1) * Dd + col0 + tx * 2 + 0] = acc10;
    g_T[(row0 + ty * 2 + 1) * Dd + col0 + tx * 2 + 1] = acc11;
    cudaTriggerProgrammaticLaunchCompletion();
}

// ---------------------------------------------------------------------------
// Kernel 3: S[b,n,m] = dot(T[b,n,:], Y[b,m,:]) + bias
// PDL-structured: stage 32x256 Y strip before grid-dep sync, then stream T.
// ys padded to 257 -> the ys[m][k] (common-k) reads are conflict-free.
// ---------------------------------------------------------------------------
__global__ void __launch_bounds__(256) k_gemm_TYt(const float* __restrict__ Y,
                                                   const float* __restrict__ bias,
                                                   float* __restrict__ out) {
    __shared__ float ys[32][257];   // full K strip of Y rows (padded)
    __shared__ float ts[32][33];    // T tile [n_local][k]
    int tx = threadIdx.x, ty = threadIdx.y;      // 16x16
    int tid = ty * 16 + tx;
    int bat = blockIdx.z;
    int n0 = blockIdx.y * 32;
    int m0 = blockIdx.x * 32;
    const float* Tb = g_T + bat * Nn * Dd;
    const float* Yb = Y + bat * Mm * Dd;

    // Stage Y strip (independent of upstream kernel)
    for (int i = tid; i < 32 * 64; i += 256) {
        int r = i >> 6, c4 = i & 63;
        float4 v = ((const float4*)(Yb + (long)(m0 + r) * Dd))[c4];
        ys[r][c4 * 4 + 0] = v.x; ys[r][c4 * 4 + 1] = v.y;
        ys[r][c4 * 4 + 2] = v.z; ys[r][c4 * 4 + 3] = v.w;
    }
    float bv = bias[0];
    cudaGridDependencySynchronize();   // g_T now visible
    __syncthreads();

    float acc00 = 0.f, acc01 = 0.f, acc10 = 0.f, acc11 = 0.f;
    for (int t = 0; t < Dd; t += 32) {
#pragma unroll
        for (int i = 0; i < 2; i++)
#pragma unroll
            for (int j = 0; j < 2; j++)
                ts[ty * 2 + i][tx * 2 + j] = Tb[(n0 + ty * 2 + i) * Dd + t + tx * 2 + j];
        __syncthreads();
#pragma unroll
        for (int k = 0; k < 32; k++) {
            float t0 = ts[ty * 2 + 0][k];
            float t1 = ts[ty * 2 + 1][k];
            float y0 = ys[tx * 2 + 0][t + k];
            float y1 = ys[tx * 2 + 1][t + k];
            acc00 += t0 * y0; acc01 += t0 * y1;
            acc10 += t1 * y0; acc11 += t1 * y1;
        }
        __syncthreads();
    }
    float* o = out + bat * Nn * Mm;
    o[(n0 + ty * 2 + 0) * Mm + m0 + tx * 2 + 0] = acc00 + bv;
    o[(n0 + ty * 2 + 0) * Mm + m0 + tx * 2 + 1] = acc01 + bv;
    o[(n0 + ty * 2 + 1) * Mm + m0 + tx * 2 + 0] = acc10 + bv;
    o[(n0 + ty * 2 + 1) * Mm + m0 + tx * 2 + 1] = acc11 + bv;
}

// ---------------------------------------------------------------------------
// Launch. Input order (metadata): X, Y, A, W, b. Output fp32 [B,N,M].
// Kernels 2 & 3 launched with programmatic-stream-serialization so their
// staging prologues overlap the upstream kernel's tail. Graph-capturable.
// ---------------------------------------------------------------------------
extern "C" void kernel_launch(void* const* d_in, const int* in_sizes, int n_in,
                              void* d_out, int out_size) {
    const float* X = (const float*)d_in[0];
    const float* Y = (const float*)d_in[1];
    const float* A = (const float*)d_in[2];
    const float* W = (const float*)d_in[3];
    const float* b = (const float*)d_in[4];
    float* out = (float*)d_out;

    // 1) Aw = A contracted with W over k: 16 rows/block, 4096 blocks
    k_reduce_A<<<(Dd * Dd) / 16, 256>>>(A, W);

    cudaLaunchAttribute attr[1];
    attr[0].id = cudaLaunchAttributeProgrammaticStreamSerialization;
    attr[0].val.programmaticStreamSerializationAllowed = 1;

    // 2) T = X @ Aw : [512,256] = [512,256] x [256,256]   (PDL)
    {
        cudaLaunchConfig_t cfg = {};
        cfg.gridDim = dim3(Dd / 32, (Bsz * Nn) / 32, 1);
        cfg.blockDim = dim3(16, 16, 1);
        cfg.stream = 0;
        cfg.attrs = attr;
        cfg.numAttrs = 1;
        cudaLaunchKernelEx(&cfg, k_gemm_XA, X);
    }

    // 3) S = T @ Y^T (+bias), batched over B   (PDL)
    {
        cudaLaunchConfig_t cfg = {};
        cfg.gridDim = dim3(Mm / 32, Nn / 32, Bsz);
        cfg.blockDim = dim3(16, 16, 1);
        cfg.stream = 0;
        cfg.attrs = attr;
        cfg.numAttrs = 1;
        cudaLaunchKernelEx(&cfg, k_gemm_TYt, Y, b, out);
    }
}